// round 14
// baseline (speedup 1.0000x reference)
#include <cuda_runtime.h>

#define N_IMG 8
#define H 32
#define W 32
#define CIN 32
#define COUT 64
#define HO 30
#define WO 30
#define NPIX (N_IMG*HO*WO)       // 7200
#define PDIM (3*3*CIN)           // 288

typedef unsigned long long u64;
typedef unsigned int u32;

// ---------------------------------------------------------------------------
// Device-global scratch (no allocation allowed in kernel_launch)
// g_v: [n*H + h][ci][w] float2 {max(x,.1), max(-x,.1)}
// g_wp: packed weight pairs, [half][k][cg][t] ulonglong2:
//   entry = { f32x2{ek[k][c0],ek[k][c0+1]}, f32x2{ek[k][c0+2],ek[k][c0+3]} }
//   c0 = half*32 + cg*4, k = 0..287, cg = 0..7, t = table 1/2
// ---------------------------------------------------------------------------
__device__ __align__(16) float2     g_v[N_IMG*H*CIN*W];
__device__ __align__(16) ulonglong2 g_wp[2*PDIM*8*2];     // 9216 entries

#define TBLOCKS (N_IMG*H)        // 256 transpose blocks
#define WITEMS  (2*PDIM*8)       // 4608 weight items
#define WBLOCKS ((WITEMS + 1023)/1024)  // 5

#define SW_ENTRIES (PDIM*8*2)    // 4608 ulonglong2 = 73728 B
#define SV_FLOAT2  (3*CIN*W + 4) // 3076 float2 (pad for j+px overread)
#define SMEM_BYTES (SW_ENTRIES*16 + SV_FLOAT2*8)   // 98336

// Two packed f32x2 multiplies, fold both ci-products into each u32 acc with
// one 3-input DPX max. Valid: all products are strictly positive finite
// floats (v >= 0.1, w = exp(k) > 0); positive IEEE floats order like u32.
__device__ __forceinline__ void mm3(u64 v0, u64 w0, u64 v1, u64 w1,
                                    u32& a0, u32& a1) {
    u32 p0lo, p0hi, p1lo, p1hi;
    asm("{\n\t"
        ".reg .b64 t0, t1;\n\t"
        "mul.rn.f32x2 t0, %4, %5;\n\t"
        "mul.rn.f32x2 t1, %6, %7;\n\t"
        "mov.b64 {%0, %1}, t0;\n\t"
        "mov.b64 {%2, %3}, t1;\n\t"
        "}"
        : "=r"(p0lo), "=r"(p0hi), "=r"(p1lo), "=r"(p1hi)
        : "l"(v0), "l"(w0), "l"(v1), "l"(w1));
    a0 = __vimax3_u32(a0, p0lo, p1lo);
    a1 = __vimax3_u32(a1, p0hi, p1hi);
}

__device__ __forceinline__ u64 pack2(float lo, float hi) {
    u64 d; asm("mov.b64 %0, {%1, %2};" : "=l"(d) : "f"(lo), "f"(hi)); return d;
}
__device__ __forceinline__ u64 packh(float lo, float hi) {
    return (u64)__float_as_uint(lo) | ((u64)__float_as_uint(hi) << 32);
}

// ---------------------------------------------------------------------------
// Fused prep (identical to R13):
//   blocks [0,TBLOCKS): clamp + NHWC -> [n,h][ci][w] float2 transpose
//   blocks [TBLOCKS,+WBLOCKS): exp(weights) into packed-pair layout
// ---------------------------------------------------------------------------
__global__ void prep(const float* __restrict__ x,
                     const float* __restrict__ k1,
                     const float* __restrict__ k2) {
    const int b = blockIdx.x;
    if (b < TBLOCKS) {
        __shared__ float tile[32][33];
        const int n = b >> 5;
        const int h = b & 31;
        {
            const int c = threadIdx.x;
            const int w = threadIdx.y;
            tile[w][c] = x[(((n*H + h)*W + w)*CIN) + c];
        }
        __syncthreads();
        {
            const int w = threadIdx.x;
            const int c = threadIdx.y;
            const float v = tile[w][c];
            g_v[((n*H + h)*CIN + c)*W + w] =
                make_float2(fmaxf(v, 0.1f), fmaxf(-v, 0.1f));
        }
    } else {
        const int item = (b - TBLOCKS)*1024 + threadIdx.y*32 + threadIdx.x;
        if (item < WITEMS) {
            const int half = item / (PDIM*8);
            const int rem  = item - half*(PDIM*8);
            const int k    = rem >> 3;
            const int cg   = rem & 7;
            const int c0   = half*32 + cg*4;
            const int base = k*COUT + c0;
            ulonglong2 e1, e2;
            e1.x = packh(expf(k1[base]),   expf(k1[base+1]));
            e1.y = packh(expf(k1[base+2]), expf(k1[base+3]));
            e2.x = packh(expf(k2[base]),   expf(k2[base+1]));
            e2.y = packh(expf(k2[base+2]), expf(k2[base+3]));
            g_wp[item*2]     = e1;
            g_wp[item*2 + 1] = e2;
        }
    }
}

// ---------------------------------------------------------------------------
// Main: CTA = 512 thr = 16 warps; blockIdx = (row 0..239) x (cout-half 0..1).
// Warp wid: wcg = wid&3 (8-cout group), ciq = wid>>2 (ci quarter, 8 ci).
// Lane: pxp = l&15 (pixel pair 2pxp, 2pxp+1), cgbit = l>>4 (4-cout quad).
// Each LANE register-blocks 2 pixels x 4 couts x 4 tables = 32 u32 accs.
// Crossbar bytes: 96B per lane per 2-ci for 64 products = 1.5 B/product
// (vs 2.5 in R13) -> ~40% less smem-return traffic, the measured binder.
// 4-way ci combine through the (dead) weight smem region at the end.
// ---------------------------------------------------------------------------
__global__ void __launch_bounds__(512, 2)
morph_main(const float* __restrict__ bias, float* __restrict__ out) {
    extern __shared__ __align__(16) char smem[];
    ulonglong2* s_w = reinterpret_cast<ulonglong2*>(smem);
    float2*     s_v = reinterpret_cast<float2*>(smem + SW_ENTRIES*16);
    u32*        s_r = reinterpret_cast<u32*>(smem);   // reused after loop

    const int tid   = threadIdx.x;
    const int wid   = tid >> 5;
    const int lane  = tid & 31;
    const int wcg   = wid & 3;         // 8-cout group within half
    const int ciq   = wid >> 2;        // ci quarter (8 ci)
    const int pxp   = lane & 15;       // pixel pair
    const int cgbit = lane >> 4;       // which 4-cout quad
    const int cg    = wcg*2 + cgbit;   // 0..7
    const int row   = blockIdx.x >> 1; // 0..239
    const int half  = blockIdx.x & 1;
    const int n     = row / HO;
    const int ho    = row - n*HO;
    const int c0    = half*32 + cg*4;  // global cout base (4 couts)

    // Stage weights for this cout-half (contiguous 73728B)
    {
        const ulonglong2* __restrict__ src = g_wp + half*SW_ENTRIES;
        for (int idx = tid; idx < SW_ENTRIES; idx += 512)
            s_w[idx] = src[idx];
    }
    // Stage v rows ho..ho+2 (contiguous: 1536 x 16B)
    {
        const ulonglong2* __restrict__ src =
            reinterpret_cast<const ulonglong2*>(g_v + (n*H + ho)*CIN*W);
        ulonglong2* dst = reinterpret_cast<ulonglong2*>(s_v);
        for (int idx = tid; idx < 3*CIN*W/2; idx += 512)
            dst[idx] = src[idx];
    }
    __syncthreads();

    // m[px][table: 11,12,21,22][cout 0..3]
    u32 m[2][4][4];
    #pragma unroll
    for (int p = 0; p < 2; p++)
        #pragma unroll
        for (int t = 0; t < 4; t++)
            #pragma unroll
            for (int c = 0; c < 4; c++) m[p][t][c] = 0u;

    #pragma unroll 1
    for (int ij = 0; ij < 9; ij++) {
        const int i = ij / 3;
        const int j = ij - 3*i;
        const float2* __restrict__ vr =
            s_v + (i*CIN + ciq*8)*W + j + 2*pxp;
        const ulonglong2* __restrict__ wp =
            s_w + ((ij*CIN + ciq*8)*8 + cg)*2;

        #pragma unroll 2
        for (int c2 = 0; c2 < 4; c2++) {
            const float2 va0 = vr[(2*c2)*W];         // px0, ci a
            const float2 va1 = vr[(2*c2)*W + 1];     // px1, ci a
            const float2 vb0 = vr[(2*c2+1)*W];       // px0, ci b
            const float2 vb1 = vr[(2*c2+1)*W + 1];   // px1, ci b
            const ulonglong2 w1a = wp[(2*c2)*16];
            const ulonglong2 w2a = wp[(2*c2)*16 + 1];
            const ulonglong2 w1b = wp[(2*c2+1)*16];
            const ulonglong2 w2b = wp[(2*c2+1)*16 + 1];

            const u64 xa0 = pack2(va0.x, va0.x), na0 = pack2(va0.y, va0.y);
            const u64 xb0 = pack2(vb0.x, vb0.x), nb0 = pack2(vb0.y, vb0.y);
            mm3(xa0, w1a.x, xb0, w1b.x, m[0][0][0], m[0][0][1]);
            mm3(xa0, w1a.y, xb0, w1b.y, m[0][0][2], m[0][0][3]);
            mm3(xa0, w2a.x, xb0, w2b.x, m[0][1][0], m[0][1][1]);
            mm3(xa0, w2a.y, xb0, w2b.y, m[0][1][2], m[0][1][3]);
            mm3(na0, w1a.x, nb0, w1b.x, m[0][2][0], m[0][2][1]);
            mm3(na0, w1a.y, nb0, w1b.y, m[0][2][2], m[0][2][3]);
            mm3(na0, w2a.x, nb0, w2b.x, m[0][3][0], m[0][3][1]);
            mm3(na0, w2a.y, nb0, w2b.y, m[0][3][2], m[0][3][3]);

            const u64 xa1 = pack2(va1.x, va1.x), na1 = pack2(va1.y, va1.y);
            const u64 xb1 = pack2(vb1.x, vb1.x), nb1 = pack2(vb1.y, vb1.y);
            mm3(xa1, w1a.x, xb1, w1b.x, m[1][0][0], m[1][0][1]);
            mm3(xa1, w1a.y, xb1, w1b.y, m[1][0][2], m[1][0][3]);
            mm3(xa1, w2a.x, xb1, w2b.x, m[1][1][0], m[1][1][1]);
            mm3(xa1, w2a.y, xb1, w2b.y, m[1][1][2], m[1][1][3]);
            mm3(na1, w1a.x, nb1, w1b.x, m[1][2][0], m[1][2][1]);
            mm3(na1, w1a.y, nb1, w1b.y, m[1][2][2], m[1][2][3]);
            mm3(na1, w2a.x, nb1, w2b.x, m[1][3][0], m[1][3][1]);
            mm3(na1, w2a.y, nb1, w2b.y, m[1][3][2], m[1][3][3]);
        }
    }

    // 4-way ci-quarter combine in the (dead) weight smem region.
    __syncthreads();   // all warps done reading s_w / s_v
    if (ciq > 0) {
        u32* dst = s_r + (((ciq-1)*4 + wcg)*32 + lane)*32;
        #pragma unroll
        for (int p = 0; p < 2; p++)
            #pragma unroll
            for (int t = 0; t < 4; t++)
                #pragma unroll
                for (int c = 0; c < 4; c++)
                    dst[(p*4 + t)*4 + c] = m[p][t][c];
    }
    __syncthreads();
    if (ciq == 0) {
        #pragma unroll
        for (int g = 0; g < 3; g++) {
            const u32* src = s_r + ((g*4 + wcg)*32 + lane)*32;
            #pragma unroll
            for (int p = 0; p < 2; p++)
                #pragma unroll
                for (int t = 0; t < 4; t++)
                    #pragma unroll
                    for (int c = 0; c < 4; c++)
                        m[p][t][c] = umax(m[p][t][c], src[(p*4 + t)*4 + c]);
        }

        const float4 bv = *reinterpret_cast<const float4*>(bias + c0);
        #pragma unroll
        for (int p = 0; p < 2; p++) {
            const int px = 2*pxp + p;
            if (px < WO) {
                const int q = (n*HO + ho)*WO + px;
                float4 res;
                res.x = __uint_as_float(m[p][0][0]) - __uint_as_float(m[p][1][0])
                      - __uint_as_float(m[p][2][0]) + __uint_as_float(m[p][3][0]) + bv.x;
                res.y = __uint_as_float(m[p][0][1]) - __uint_as_float(m[p][1][1])
                      - __uint_as_float(m[p][2][1]) + __uint_as_float(m[p][3][1]) + bv.y;
                res.z = __uint_as_float(m[p][0][2]) - __uint_as_float(m[p][1][2])
                      - __uint_as_float(m[p][2][2]) + __uint_as_float(m[p][3][2]) + bv.z;
                res.w = __uint_as_float(m[p][0][3]) - __uint_as_float(m[p][1][3])
                      - __uint_as_float(m[p][2][3]) + __uint_as_float(m[p][3][3]) + bv.w;
                *reinterpret_cast<float4*>(out + (size_t)q*COUT + c0) = res;
            }
        }
    }
}

// ---------------------------------------------------------------------------
extern "C" void kernel_launch(void* const* d_in, const int* in_sizes, int n_in,
                              void* d_out, int out_size) {
    const float* x    = (const float*)d_in[0];
    const float* k1   = (const float*)d_in[1];
    const float* k2   = (const float*)d_in[2];
    const float* bias = (const float*)d_in[3];
    float* out = (float*)d_out;

    cudaFuncSetAttribute(morph_main,
                         cudaFuncAttributeMaxDynamicSharedMemorySize,
                         SMEM_BYTES);

    prep<<<TBLOCKS + WBLOCKS, dim3(32,32)>>>(x, k1, k2);
    morph_main<<<HO*N_IMG*2, 512, SMEM_BYTES>>>(bias, out);
}

// round 15
// speedup vs baseline: 1.9733x; 1.9733x over previous
#include <cuda_runtime.h>

#define N_IMG 8
#define H 32
#define W 32
#define CIN 32
#define COUT 64
#define HO 30
#define WO 30
#define NPIX (N_IMG*HO*WO)       // 7200
#define PDIM (3*3*CIN)           // 288

typedef unsigned long long u64;
typedef unsigned int u32;

// ---------------------------------------------------------------------------
// Device-global scratch (no allocation allowed in kernel_launch)
// g_v: [n*H + h][ci][w] float2 {max(x,.1), max(-x,.1)}
// g_wp: packed weight pairs, [half][k][cg][t] ulonglong2:
//   entry = { f32x2{ek[k][c0],ek[k][c0+1]}, f32x2{ek[k][c0+2],ek[k][c0+3]} }
//   c0 = half*32 + cg*4, k = 0..287, cg = 0..7, t = table 1/2
// ---------------------------------------------------------------------------
__device__ __align__(16) float2     g_v[N_IMG*H*CIN*W];
__device__ __align__(16) ulonglong2 g_wp[2*PDIM*8*2];     // 9216 entries

#define TBLOCKS (N_IMG*H)        // 256 transpose blocks
#define WITEMS  (2*PDIM*8)       // 4608 weight items
#define WBLOCKS ((WITEMS + 1023)/1024)  // 5

#define SW_ENTRIES (PDIM*8*2)    // 4608 ulonglong2 = 73728 B
#define SV_FLOAT2  (3*CIN*W + 4) // 3076 float2 (pad for j+px overread)
#define SMEM_BYTES (SW_ENTRIES*16 + SV_FLOAT2*8)   // 98336

// Two packed f32x2 multiplies, fold both ci-products into each u32 acc with
// one 3-input DPX max. Valid: all products are strictly positive finite
// floats (v >= 0.1, w = exp(k) > 0); positive IEEE floats order like u32.
__device__ __forceinline__ void mm3(u64 v0, u64 w0, u64 v1, u64 w1,
                                    u32& a0, u32& a1) {
    u32 p0lo, p0hi, p1lo, p1hi;
    asm("{\n\t"
        ".reg .b64 t0, t1;\n\t"
        "mul.rn.f32x2 t0, %4, %5;\n\t"
        "mul.rn.f32x2 t1, %6, %7;\n\t"
        "mov.b64 {%0, %1}, t0;\n\t"
        "mov.b64 {%2, %3}, t1;\n\t"
        "}"
        : "=r"(p0lo), "=r"(p0hi), "=r"(p1lo), "=r"(p1hi)
        : "l"(v0), "l"(w0), "l"(v1), "l"(w1));
    a0 = __vimax3_u32(a0, p0lo, p1lo);
    a1 = __vimax3_u32(a1, p0hi, p1hi);
}

__device__ __forceinline__ u64 pack2(float lo, float hi) {
    u64 d; asm("mov.b64 %0, {%1, %2};" : "=l"(d) : "f"(lo), "f"(hi)); return d;
}
__device__ __forceinline__ u64 packh(float lo, float hi) {
    return (u64)__float_as_uint(lo) | ((u64)__float_as_uint(hi) << 32);
}

// ---------------------------------------------------------------------------
// Fused prep (identical to R12/R13):
//   blocks [0,TBLOCKS): clamp + NHWC -> [n,h][ci][w] float2 transpose
//   blocks [TBLOCKS,+WBLOCKS): exp(weights) into packed-pair layout
// ---------------------------------------------------------------------------
__global__ void prep(const float* __restrict__ x,
                     const float* __restrict__ k1,
                     const float* __restrict__ k2) {
    const int b = blockIdx.x;
    if (b < TBLOCKS) {
        __shared__ float tile[32][33];
        const int n = b >> 5;
        const int h = b & 31;
        {
            const int c = threadIdx.x;
            const int w = threadIdx.y;
            tile[w][c] = x[(((n*H + h)*W + w)*CIN) + c];
        }
        __syncthreads();
        {
            const int w = threadIdx.x;
            const int c = threadIdx.y;
            const float v = tile[w][c];
            g_v[((n*H + h)*CIN + c)*W + w] =
                make_float2(fmaxf(v, 0.1f), fmaxf(-v, 0.1f));
        }
    } else {
        const int item = (b - TBLOCKS)*1024 + threadIdx.y*32 + threadIdx.x;
        if (item < WITEMS) {
            const int half = item / (PDIM*8);
            const int rem  = item - half*(PDIM*8);
            const int k    = rem >> 3;
            const int cg   = rem & 7;
            const int c0   = half*32 + cg*4;
            const int base = k*COUT + c0;
            ulonglong2 e1, e2;
            e1.x = packh(expf(k1[base]),   expf(k1[base+1]));
            e1.y = packh(expf(k1[base+2]), expf(k1[base+3]));
            e2.x = packh(expf(k2[base]),   expf(k2[base+1]));
            e2.y = packh(expf(k2[base+2]), expf(k2[base+3]));
            g_wp[item*2]     = e1;
            g_wp[item*2 + 1] = e2;
        }
    }
}

// ---------------------------------------------------------------------------
// Main: CTA = 256 thr = 8 warps; blockIdx = (row 0..239) x (cout-half 0..1).
// Warp wid: wcg = wid&3 (8-cout group), cih = wid>>2 (ci half, 16 ci).
// Lane: pxp = l&15 (pixel pair), cgbit = l>>4 (4-cout quad).
// Each LANE register-blocks 2 pixels x 4 couts x 4 tables = 32 u32 accs.
// Crossbar bytes: 1.5 B/product (vs 2.5 in R13). 256 thr + 128-reg cap
// (launch_bounds(256,2)) gives the 32 accs room WITHOUT spilling (R14's
// failure was the 64-reg cap from 512 thr).
// 2-way ci combine through the (dead) weight smem region at the end.
// ---------------------------------------------------------------------------
__global__ void __launch_bounds__(256, 2)
morph_main(const float* __restrict__ bias, float* __restrict__ out) {
    extern __shared__ __align__(16) char smem[];
    ulonglong2* s_w = reinterpret_cast<ulonglong2*>(smem);
    float2*     s_v = reinterpret_cast<float2*>(smem + SW_ENTRIES*16);
    u32*        s_r = reinterpret_cast<u32*>(smem);   // reused after loop

    const int tid   = threadIdx.x;
    const int wid   = tid >> 5;
    const int lane  = tid & 31;
    const int wcg   = wid & 3;         // 8-cout group within half
    const int cih   = wid >> 2;        // ci half (16 ci)
    const int pxp   = lane & 15;       // pixel pair
    const int cgbit = lane >> 4;       // which 4-cout quad
    const int cg    = wcg*2 + cgbit;   // 0..7
    const int row   = blockIdx.x >> 1; // 0..239
    const int half  = blockIdx.x & 1;
    const int n     = row / HO;
    const int ho    = row - n*HO;
    const int c0    = half*32 + cg*4;  // global cout base (4 couts)

    // Stage weights for this cout-half (contiguous 73728B)
    {
        const ulonglong2* __restrict__ src = g_wp + half*SW_ENTRIES;
        for (int idx = tid; idx < SW_ENTRIES; idx += 256)
            s_w[idx] = src[idx];
    }
    // Stage v rows ho..ho+2 (contiguous: 1536 x 16B)
    {
        const ulonglong2* __restrict__ src =
            reinterpret_cast<const ulonglong2*>(g_v + (n*H + ho)*CIN*W);
        ulonglong2* dst = reinterpret_cast<ulonglong2*>(s_v);
        for (int idx = tid; idx < 3*CIN*W/2; idx += 256)
            dst[idx] = src[idx];
    }
    __syncthreads();

    // m[px][table: 11,12,21,22][cout 0..3]
    u32 m[2][4][4];
    #pragma unroll
    for (int p = 0; p < 2; p++)
        #pragma unroll
        for (int t = 0; t < 4; t++)
            #pragma unroll
            for (int c = 0; c < 4; c++) m[p][t][c] = 0u;

    #pragma unroll 1
    for (int ij = 0; ij < 9; ij++) {
        const int i = ij / 3;
        const int j = ij - 3*i;
        const float2* __restrict__ vr =
            s_v + (i*CIN + cih*16)*W + j + 2*pxp;
        const ulonglong2* __restrict__ wp =
            s_w + ((ij*CIN + cih*16)*8 + cg)*2;

        #pragma unroll 2
        for (int c2 = 0; c2 < 8; c2++) {
            const float2 va0 = vr[(2*c2)*W];         // px0, ci a
            const float2 va1 = vr[(2*c2)*W + 1];     // px1, ci a
            const float2 vb0 = vr[(2*c2+1)*W];       // px0, ci b
            const float2 vb1 = vr[(2*c2+1)*W + 1];   // px1, ci b
            const ulonglong2 w1a = wp[(2*c2)*16];
            const ulonglong2 w2a = wp[(2*c2)*16 + 1];
            const ulonglong2 w1b = wp[(2*c2+1)*16];
            const ulonglong2 w2b = wp[(2*c2+1)*16 + 1];

            const u64 xa0 = pack2(va0.x, va0.x), na0 = pack2(va0.y, va0.y);
            const u64 xb0 = pack2(vb0.x, vb0.x), nb0 = pack2(vb0.y, vb0.y);
            mm3(xa0, w1a.x, xb0, w1b.x, m[0][0][0], m[0][0][1]);
            mm3(xa0, w1a.y, xb0, w1b.y, m[0][0][2], m[0][0][3]);
            mm3(xa0, w2a.x, xb0, w2b.x, m[0][1][0], m[0][1][1]);
            mm3(xa0, w2a.y, xb0, w2b.y, m[0][1][2], m[0][1][3]);
            mm3(na0, w1a.x, nb0, w1b.x, m[0][2][0], m[0][2][1]);
            mm3(na0, w1a.y, nb0, w1b.y, m[0][2][2], m[0][2][3]);
            mm3(na0, w2a.x, nb0, w2b.x, m[0][3][0], m[0][3][1]);
            mm3(na0, w2a.y, nb0, w2b.y, m[0][3][2], m[0][3][3]);

            const u64 xa1 = pack2(va1.x, va1.x), na1 = pack2(va1.y, va1.y);
            const u64 xb1 = pack2(vb1.x, vb1.x), nb1 = pack2(vb1.y, vb1.y);
            mm3(xa1, w1a.x, xb1, w1b.x, m[1][0][0], m[1][0][1]);
            mm3(xa1, w1a.y, xb1, w1b.y, m[1][0][2], m[1][0][3]);
            mm3(xa1, w2a.x, xb1, w2b.x, m[1][1][0], m[1][1][1]);
            mm3(xa1, w2a.y, xb1, w2b.y, m[1][1][2], m[1][1][3]);
            mm3(na1, w1a.x, nb1, w1b.x, m[1][2][0], m[1][2][1]);
            mm3(na1, w1a.y, nb1, w1b.y, m[1][2][2], m[1][2][3]);
            mm3(na1, w2a.x, nb1, w2b.x, m[1][3][0], m[1][3][1]);
            mm3(na1, w2a.y, nb1, w2b.y, m[1][3][2], m[1][3][3]);
        }
    }

    // 2-way ci-half combine in the (dead) weight smem region.
    __syncthreads();   // all warps done reading s_w / s_v
    if (cih == 1) {
        u32* dst = s_r + ((wcg*32 + lane)*32);
        #pragma unroll
        for (int p = 0; p < 2; p++)
            #pragma unroll
            for (int t = 0; t < 4; t++)
                #pragma unroll
                for (int c = 0; c < 4; c++)
                    dst[(p*4 + t)*4 + c] = m[p][t][c];
    }
    __syncthreads();
    if (cih == 0) {
        const u32* src = s_r + ((wcg*32 + lane)*32);
        #pragma unroll
        for (int p = 0; p < 2; p++)
            #pragma unroll
            for (int t = 0; t < 4; t++)
                #pragma unroll
                for (int c = 0; c < 4; c++)
                    m[p][t][c] = umax(m[p][t][c], src[(p*4 + t)*4 + c]);

        const float4 bv = *reinterpret_cast<const float4*>(bias + c0);
        #pragma unroll
        for (int p = 0; p < 2; p++) {
            const int px = 2*pxp + p;
            if (px < WO) {
                const int q = (n*HO + ho)*WO + px;
                float4 res;
                res.x = __uint_as_float(m[p][0][0]) - __uint_as_float(m[p][1][0])
                      - __uint_as_float(m[p][2][0]) + __uint_as_float(m[p][3][0]) + bv.x;
                res.y = __uint_as_float(m[p][0][1]) - __uint_as_float(m[p][1][1])
                      - __uint_as_float(m[p][2][1]) + __uint_as_float(m[p][3][1]) + bv.y;
                res.z = __uint_as_float(m[p][0][2]) - __uint_as_float(m[p][1][2])
                      - __uint_as_float(m[p][2][2]) + __uint_as_float(m[p][3][2]) + bv.z;
                res.w = __uint_as_float(m[p][0][3]) - __uint_as_float(m[p][1][3])
                      - __uint_as_float(m[p][2][3]) + __uint_as_float(m[p][3][3]) + bv.w;
                *reinterpret_cast<float4*>(out + (size_t)q*COUT + c0) = res;
            }
        }
    }
}

// ---------------------------------------------------------------------------
extern "C" void kernel_launch(void* const* d_in, const int* in_sizes, int n_in,
                              void* d_out, int out_size) {
    const float* x    = (const float*)d_in[0];
    const float* k1   = (const float*)d_in[1];
    const float* k2   = (const float*)d_in[2];
    const float* bias = (const float*)d_in[3];
    float* out = (float*)d_out;

    cudaFuncSetAttribute(morph_main,
                         cudaFuncAttributeMaxDynamicSharedMemorySize,
                         SMEM_BYTES);

    prep<<<TBLOCKS + WBLOCKS, dim3(32,32)>>>(x, k1, k2);
    morph_main<<<HO*N_IMG*2, 256, SMEM_BYTES>>>(bias, out);
}